// round 9
// baseline (speedup 1.0000x reference)
#include <cuda_runtime.h>
#include <cstdint>

// LinearAttention: B=16, DK=64, N=8192, DV=64, fp32.
//   ktv[b,k,j] = sum_n k[b,n,k] * v[b,n,j]
//   out[b,n,j] = sum_k q[b,k,n] * ktv[b,k,j]
// Inputs: q [B,DK,N], k [B,N,DK], v [B,N,DV]. Output [B,N,DV] fp32.
//
// Tensor cores via mma.sync.m16n8k8.tf32, 3-pass hi/lo split (3xTF32).
// B-operand hi/lo splits are precomputed into smem ONCE (they were 4x
// redundant across warps); A-operand splits stay in-loop (non-redundant).

#define BATCH  16
#define DKC    64
#define NSEQ   8192
#define DVC    64
#define S1B    32                 // phase-1 blocks per batch
#define ROWS_PB (NSEQ / S1B)      // 256
#define TROWS  32
#define NTILES (ROWS_PB / TROWS)  // 8
#define KS     68                 // phase1 k fp32 smem stride (words)
#define VS     132                // phase1 v hi/lo interleaved stride (words)
#define QS     130                // phase2 q fp32 stride
#define KTS    68                 // phase2 ktv hi/lo (separate tiles) stride

#define P1_SMEM ((2 * TROWS * KS + 2 * TROWS * VS) * 4)          // 51200 B
#define P2_SMEM ((DKC * QS + 2 * DKC * KTS) * 4)                 // 68096 B

__device__ float g_part[BATCH * S1B * DKC * DVC];  // 8 MB partial ktv
__device__ float g_ktv [BATCH * DKC * DVC];

// ---------------- helpers ----------------
__device__ __forceinline__ void cp16(uint32_t dst, const void* src) {
    asm volatile("cp.async.cg.shared.global [%0], [%1], 16;" :: "r"(dst), "l"(src));
}
__device__ __forceinline__ void cp_commit() { asm volatile("cp.async.commit_group;"); }
__device__ __forceinline__ void cp_wait0()  { asm volatile("cp.async.wait_group 0;"); }
__device__ __forceinline__ uint32_t smem_u32(const void* p) {
    uint32_t a;
    asm("{ .reg .u64 t; cvta.to.shared.u64 t, %1; cvt.u32.u64 %0, t; }" : "=r"(a) : "l"(p));
    return a;
}
__device__ __forceinline__ uint32_t tf32_of(float x) {
    uint32_t r; asm("cvt.rna.tf32.f32 %0, %1;" : "=r"(r) : "f"(x)); return r;
}
__device__ __forceinline__ void tf32_split(float x, uint32_t& hi, uint32_t& lo) {
    hi = tf32_of(x);
    lo = tf32_of(x - __uint_as_float(hi));
}
__device__ __forceinline__ void mma_tf32(float* d,
                                         uint32_t a0, uint32_t a1, uint32_t a2, uint32_t a3,
                                         uint32_t b0, uint32_t b1) {
    asm volatile("mma.sync.aligned.m16n8k8.row.col.f32.tf32.tf32.f32 "
                 "{%0,%1,%2,%3}, {%4,%5,%6,%7}, {%8,%9}, {%0,%1,%2,%3};"
                 : "+f"(d[0]), "+f"(d[1]), "+f"(d[2]), "+f"(d[3])
                 : "r"(a0), "r"(a1), "r"(a2), "r"(a3), "r"(b0), "r"(b1));
}

// ============================================================================
// Phase 1: partial ktv = k_chunk^T @ v_chunk.
// Block 128 thr (4 warps). Warp w: dk rows [16w,16w+16) x all 64 j.
// mma: m=dk, k=n, n'=j.  A = k_tile[n][dk] fp32 (split in-loop);
// B = v_tile[n][j] pre-split hi/lo interleaved (word off = r*VS+g*16+jt*2).
// k via cp.async double-buffer; v via LDG->convert->STS double-buffer.
// ============================================================================
__global__ __launch_bounds__(128) void phase1_kernel(
    const float* __restrict__ kmat, const float* __restrict__ vmat)
{
    extern __shared__ uint32_t p1sm[];
    float*    ks = (float*)p1sm;             // [2][TROWS][KS]
    uint32_t* vs = p1sm + 2 * TROWS * KS;    // [2][TROWS][VS]

    const int b    = blockIdx.y;
    const int blk  = blockIdx.x;
    const int t    = threadIdx.x;
    const int w    = t >> 5;
    const int lane = t & 31;
    const int g    = lane >> 2;
    const int tg   = lane & 3;
    const int kd0  = 16 * w;

    float acc[8][4];
#pragma unroll
    for (int jt = 0; jt < 8; jt++)
#pragma unroll
        for (int p = 0; p < 4; p++) acc[jt][p] = 0.f;

    const long base = ((long)b * NSEQ + (long)blk * ROWS_PB) * 64;
    const float4* kg4 = (const float4*)(kmat + base);
    const float4* vg4 = (const float4*)(vmat + base);
    const uint32_t ks_addr = smem_u32(ks);

    // ---- k tile T -> ks[buf] via cp.async ----
    auto cp_k = [&](int buf, int T) {
        const float4* kp = kg4 + T * 512;
        uint32_t kb = ks_addr + (uint32_t)buf * TROWS * KS * 4;
#pragma unroll
        for (int i = 0; i < 4; i++) {
            int idx = t + i * 128;
            int r = idx >> 4, c4 = idx & 15;
            cp16(kb + (uint32_t)(r * KS + c4 * 4) * 4, kp + idx);
        }
        cp_commit();
    };
    // ---- v tile regs ----
    float4 vf[4];
    auto ldg_v = [&](int T) {
        const float4* vp = vg4 + T * 512;
#pragma unroll
        for (int i = 0; i < 4; i++) vf[i] = vp[t + i * 128];
    };
    // ---- convert vf -> vs[buf] (hi/lo interleaved, permuted g-major) ----
    auto sts_v = [&](int buf) {
        uint32_t* vb = vs + buf * TROWS * VS;
#pragma unroll
        for (int i = 0; i < 4; i++) {
            int idx = t + i * 128;
            int r = idx >> 4, c4 = (idx & 15) * 4;
            float fe[4] = { vf[i].x, vf[i].y, vf[i].z, vf[i].w };
#pragma unroll
            for (int e = 0; e < 4; e++) {
                int j = c4 + e;
                int gg = j & 7, jt = j >> 3;
                uint32_t hi, lo;
                tf32_split(fe[e], hi, lo);
                *(uint2*)(vb + r * VS + gg * 16 + jt * 2) = make_uint2(hi, lo);
            }
        }
    };

    cp_k(0, 0);
    ldg_v(0);

    for (int T = 0; T < NTILES; T++) {
        const int buf = T & 1;
        cp_wait0();
        sts_v(buf);
        __syncthreads();
        if (T + 1 < NTILES) {
            cp_k(buf ^ 1, T + 1);
            ldg_v(T + 1);
        }

        const float*    kbuf = ks + buf * TROWS * KS;
        const uint32_t* vbuf = vs + buf * TROWS * VS;

#pragma unroll
        for (int nb = 0; nb < TROWS; nb += 8) {
            const int r0 = nb + tg;
            const int r1 = r0 + 4;
            // A: fp32 loads + split (non-redundant)
            uint32_t ah[4], al[4];
            tf32_split(kbuf[r0 * KS + kd0 + g],     ah[0], al[0]);
            tf32_split(kbuf[r0 * KS + kd0 + g + 8], ah[1], al[1]);
            tf32_split(kbuf[r1 * KS + kd0 + g],     ah[2], al[2]);
            tf32_split(kbuf[r1 * KS + kd0 + g + 8], ah[3], al[3]);
            // B: vectorized pre-split loads
            const uint32_t* p0 = vbuf + r0 * VS + g * 16;
            const uint32_t* p1 = vbuf + r1 * VS + g * 16;
            uint4 b0[4], b1[4];
#pragma unroll
            for (int qv = 0; qv < 4; qv++) {
                b0[qv] = *(const uint4*)(p0 + qv * 4);
                b1[qv] = *(const uint4*)(p1 + qv * 4);
            }
            uint32_t BH0[8], BL0[8], BH1[8], BL1[8];
#pragma unroll
            for (int qv = 0; qv < 4; qv++) {
                BH0[2*qv] = b0[qv].x; BL0[2*qv] = b0[qv].y;
                BH0[2*qv+1] = b0[qv].z; BL0[2*qv+1] = b0[qv].w;
                BH1[2*qv] = b1[qv].x; BL1[2*qv] = b1[qv].y;
                BH1[2*qv+1] = b1[qv].z; BL1[2*qv+1] = b1[qv].w;
            }
#pragma unroll
            for (int jt = 0; jt < 8; jt++) {
                mma_tf32(acc[jt], ah[0], ah[1], ah[2], ah[3], BH0[jt], BH1[jt]);
                mma_tf32(acc[jt], ah[0], ah[1], ah[2], ah[3], BL0[jt], BL1[jt]);
                mma_tf32(acc[jt], al[0], al[1], al[2], al[3], BH0[jt], BH1[jt]);
            }
        }
    }

    float* p = g_part + ((long)(b * S1B + blk)) * (DKC * DVC);
#pragma unroll
    for (int jt = 0; jt < 8; jt++) {
        const int j = jt * 8 + 2 * tg;
        *(float2*)(p + (kd0 + g) * DVC + j)     = make_float2(acc[jt][0], acc[jt][1]);
        *(float2*)(p + (kd0 + g + 8) * DVC + j) = make_float2(acc[jt][2], acc[jt][3]);
    }
}

// ============================================================================
// Phase 1b: fold S1B partials -> g_ktv
// ============================================================================
__global__ __launch_bounds__(256) void reduce_kernel()
{
    const int o = blockIdx.x * 256 + threadIdx.x;
    const int b = o >> 12;
    const int r = o & 4095;
    const float* p = g_part + (long)b * S1B * 4096 + r;
    float s = 0.f;
#pragma unroll 8
    for (int i = 0; i < S1B; i++) s += p[i * 4096];
    g_ktv[o] = s;
}

// ============================================================================
// Phase 2: out = q^T @ ktv.
// Block 128 thr (4 warps), 128-row n-tile. mma: m=n, k=dk, n'=j.
// A = q_tile[dk][n] fp32 (split in-loop, non-redundant);
// B = ktv pre-split to kthi/ktlo, permuted g-major (word = dk*KTS + g*8 + jt).
// ============================================================================
__global__ __launch_bounds__(128) void phase2_kernel(
    const float* __restrict__ q, float* __restrict__ out)
{
    extern __shared__ uint32_t p2sm[];
    float*    qs   = (float*)p2sm;            // [64][QS]
    uint32_t* kthi = p2sm + DKC * QS;         // [64][KTS]
    uint32_t* ktlo = kthi + DKC * KTS;

    const int b    = blockIdx.y;
    const int n0   = blockIdx.x * 128;
    const int t    = threadIdx.x;
    const int w    = t >> 5;
    const int lane = t & 31;
    const int g    = lane >> 2;
    const int tg   = lane & 3;

    // stage ktv: split once per element
    {
        const float* src = g_ktv + b * (DKC * DVC);
#pragma unroll
        for (int i = 0; i < 32; i++) {
            int idx = t + i * 128;
            int dk = idx >> 6, j = idx & 63;
            uint32_t hi, lo;
            tf32_split(src[idx], hi, lo);
            int off = dk * KTS + (j & 7) * 8 + (j >> 3);
            kthi[off] = hi;
            ktlo[off] = lo;
        }
    }
    // stage q tile fp32 (coalesced along n)
    {
        const float* qp = q + (long)b * DKC * NSEQ + n0 + t;
#pragma unroll 8
        for (int kd = 0; kd < DKC; kd++)
            qs[kd * QS + t] = qp[(long)kd * NSEQ];
    }
    __syncthreads();

    float acc[2][8][4];
#pragma unroll
    for (int mt = 0; mt < 2; mt++)
#pragma unroll
        for (int jt = 0; jt < 8; jt++)
#pragma unroll
            for (int p = 0; p < 4; p++) acc[mt][jt][p] = 0.f;

#pragma unroll
    for (int ksp = 0; ksp < 8; ksp++) {
        const int r0 = ksp * 8 + tg;
        const int r1 = r0 + 4;

        const uint32_t* h0 = kthi + r0 * KTS + g * 8;
        const uint32_t* h1 = kthi + r1 * KTS + g * 8;
        const uint32_t* l0 = ktlo + r0 * KTS + g * 8;
        const uint32_t* l1 = ktlo + r1 * KTS + g * 8;
        uint4 H0a = *(const uint4*)h0, H0b = *(const uint4*)(h0 + 4);
        uint4 H1a = *(const uint4*)h1, H1b = *(const uint4*)(h1 + 4);
        uint4 L0a = *(const uint4*)l0, L0b = *(const uint4*)(l0 + 4);
        uint4 L1a = *(const uint4*)l1, L1b = *(const uint4*)(l1 + 4);
        uint32_t BH0[8] = {H0a.x,H0a.y,H0a.z,H0a.w,H0b.x,H0b.y,H0b.z,H0b.w};
        uint32_t BH1[8] = {H1a.x,H1a.y,H1a.z,H1a.w,H1b.x,H1b.y,H1b.z,H1b.w};
        uint32_t BL0[8] = {L0a.x,L0a.y,L0a.z,L0a.w,L0b.x,L0b.y,L0b.z,L0b.w};
        uint32_t BL1[8] = {L1a.x,L1a.y,L1a.z,L1a.w,L1b.x,L1b.y,L1b.z,L1b.w};

#pragma unroll
        for (int mt = 0; mt < 2; mt++) {
            const int nb = 32 * w + 16 * mt;
            uint32_t ah[4], al[4];
            tf32_split(qs[r0 * QS + nb + g],     ah[0], al[0]);
            tf32_split(qs[r0 * QS + nb + g + 8], ah[1], al[1]);
            tf32_split(qs[r1 * QS + nb + g],     ah[2], al[2]);
            tf32_split(qs[r1 * QS + nb + g + 8], ah[3], al[3]);
#pragma unroll
            for (int jt = 0; jt < 8; jt++) {
                mma_tf32(acc[mt][jt], ah[0], ah[1], ah[2], ah[3], BH0[jt], BH1[jt]);
                mma_tf32(acc[mt][jt], ah[0], ah[1], ah[2], ah[3], BL0[jt], BL1[jt]);
                mma_tf32(acc[mt][jt], al[0], al[1], al[2], al[3], BH0[jt], BH1[jt]);
            }
        }
    }

#pragma unroll
    for (int mt = 0; mt < 2; mt++) {
        const int nrow = n0 + 32 * w + 16 * mt + g;
        float* o0 = out + ((long)b * NSEQ + nrow) * DVC;
        float* o1 = out + ((long)b * NSEQ + nrow + 8) * DVC;
#pragma unroll
        for (int jt = 0; jt < 8; jt++) {
            const int j = jt * 8 + 2 * tg;
            *(float2*)(o0 + j) = make_float2(acc[mt][jt][0], acc[mt][jt][1]);
            *(float2*)(o1 + j) = make_float2(acc[mt][jt][2], acc[mt][jt][3]);
        }
    }
}

extern "C" void kernel_launch(void* const* d_in, const int* in_sizes, int n_in,
                              void* d_out, int out_size)
{
    const float* q = (const float*)d_in[0];
    const float* k = (const float*)d_in[1];
    const float* v = (const float*)d_in[2];
    float* out = (float*)d_out;

    cudaFuncSetAttribute(phase1_kernel, cudaFuncAttributeMaxDynamicSharedMemorySize, P1_SMEM);
    cudaFuncSetAttribute(phase2_kernel, cudaFuncAttributeMaxDynamicSharedMemorySize, P2_SMEM);

    phase1_kernel<<<dim3(S1B, BATCH), 128, P1_SMEM>>>(k, v);
    reduce_kernel<<<(BATCH * DKC * DVC) / 256, 256>>>();
    phase2_kernel<<<dim3(NSEQ / 128, BATCH), 128, P2_SMEM>>>(q, out);
}

// round 11
// speedup vs baseline: 1.1282x; 1.1282x over previous
#include <cuda_runtime.h>
#include <cstdint>

// LinearAttention: B=16, DK=64, N=8192, DV=64, fp32.
//   ktv[b,k,j] = sum_n k[b,n,k] * v[b,n,j]
//   out[b,n,j] = sum_k q[b,k,n] * ktv[b,k,j]
// Inputs: q [B,DK,N], k [B,N,DK], v [B,N,DV]. Output [B,N,DV] fp32.
//
// Tensor cores via mma.sync.m16n8k8.tf32, 3-pass hi/lo split (3xTF32).
// Phase1: grid doubled (S1B=64) to fix grid-limited occupancy (18%->~30%).
// Phase2: R7's proven 52KB/4-blocks-per-SM version (R8's 68KB variant lost).

#define BATCH  16
#define DKC    64
#define NSEQ   8192
#define DVC    64
#define S1B    64                 // phase-1 blocks per batch (was 32)
#define ROWS_PB (NSEQ / S1B)      // 128
#define TROWS  32
#define NTILES (ROWS_PB / TROWS)  // 4
#define KS     68                 // phase1 k fp32 smem stride (words)
#define VS     132                // phase1 v hi/lo interleaved stride (words)
#define P2_QSTRIDE 136
#define P2_KSTRIDE 72

#define P1_SMEM ((2 * TROWS * KS + 2 * TROWS * VS) * 4)   // 51200 B

__device__ float g_part[BATCH * S1B * DKC * DVC];  // 16 MB partial ktv
__device__ float g_ktv [BATCH * DKC * DVC];

// ---------------- helpers ----------------
__device__ __forceinline__ void cp16(uint32_t dst, const void* src) {
    asm volatile("cp.async.cg.shared.global [%0], [%1], 16;" :: "r"(dst), "l"(src));
}
__device__ __forceinline__ void cp_commit() { asm volatile("cp.async.commit_group;"); }
__device__ __forceinline__ void cp_wait0()  { asm volatile("cp.async.wait_group 0;"); }
__device__ __forceinline__ uint32_t smem_u32(const void* p) {
    uint32_t a;
    asm("{ .reg .u64 t; cvta.to.shared.u64 t, %1; cvt.u32.u64 %0, t; }" : "=r"(a) : "l"(p));
    return a;
}
__device__ __forceinline__ uint32_t tf32_of(float x) {
    uint32_t r; asm("cvt.rna.tf32.f32 %0, %1;" : "=r"(r) : "f"(x)); return r;
}
__device__ __forceinline__ void tf32_split(float x, uint32_t& hi, uint32_t& lo) {
    hi = tf32_of(x);
    lo = tf32_of(x - __uint_as_float(hi));
}
__device__ __forceinline__ void mma_tf32(float* d,
                                         uint32_t a0, uint32_t a1, uint32_t a2, uint32_t a3,
                                         uint32_t b0, uint32_t b1) {
    asm volatile("mma.sync.aligned.m16n8k8.row.col.f32.tf32.tf32.f32 "
                 "{%0,%1,%2,%3}, {%4,%5,%6,%7}, {%8,%9}, {%0,%1,%2,%3};"
                 : "+f"(d[0]), "+f"(d[1]), "+f"(d[2]), "+f"(d[3])
                 : "r"(a0), "r"(a1), "r"(a2), "r"(a3), "r"(b0), "r"(b1));
}

// ============================================================================
// Phase 1: partial ktv = k_chunk^T @ v_chunk.
// Block 128 thr (4 warps). Warp w: dk rows [16w,16w+16) x all 64 j.
// mma: m=dk, k=n, n'=j.  A = k_tile[n][dk] fp32 (split in-loop);
// B = v_tile[n][j] pre-split hi/lo interleaved (word off = r*VS+g*16+jt*2).
// k via cp.async double-buffer; v via LDG->convert->STS double-buffer.
// ============================================================================
__global__ __launch_bounds__(128, 4) void phase1_kernel(
    const float* __restrict__ kmat, const float* __restrict__ vmat)
{
    extern __shared__ uint32_t p1sm[];
    float*    ks = (float*)p1sm;             // [2][TROWS][KS]
    uint32_t* vs = p1sm + 2 * TROWS * KS;    // [2][TROWS][VS]

    const int b    = blockIdx.y;
    const int blk  = blockIdx.x;
    const int t    = threadIdx.x;
    const int w    = t >> 5;
    const int lane = t & 31;
    const int g    = lane >> 2;
    const int tg   = lane & 3;
    const int kd0  = 16 * w;

    float acc[8][4];
#pragma unroll
    for (int jt = 0; jt < 8; jt++)
#pragma unroll
        for (int p = 0; p < 4; p++) acc[jt][p] = 0.f;

    const long base = ((long)b * NSEQ + (long)blk * ROWS_PB) * 64;
    const float4* kg4 = (const float4*)(kmat + base);
    const float4* vg4 = (const float4*)(vmat + base);
    const uint32_t ks_addr = smem_u32(ks);

    auto cp_k = [&](int buf, int T) {
        const float4* kp = kg4 + T * 512;
        uint32_t kb = ks_addr + (uint32_t)buf * TROWS * KS * 4;
#pragma unroll
        for (int i = 0; i < 4; i++) {
            int idx = t + i * 128;
            int r = idx >> 4, c4 = idx & 15;
            cp16(kb + (uint32_t)(r * KS + c4 * 4) * 4, kp + idx);
        }
        cp_commit();
    };
    float4 vf[4];
    auto ldg_v = [&](int T) {
        const float4* vp = vg4 + T * 512;
#pragma unroll
        for (int i = 0; i < 4; i++) vf[i] = vp[t + i * 128];
    };
    auto sts_v = [&](int buf) {
        uint32_t* vb = vs + buf * TROWS * VS;
#pragma unroll
        for (int i = 0; i < 4; i++) {
            int idx = t + i * 128;
            int r = idx >> 4, c4 = (idx & 15) * 4;
            float fe[4] = { vf[i].x, vf[i].y, vf[i].z, vf[i].w };
#pragma unroll
            for (int e = 0; e < 4; e++) {
                int j = c4 + e;
                int gg = j & 7, jt = j >> 3;
                uint32_t hi, lo;
                tf32_split(fe[e], hi, lo);
                *(uint2*)(vb + r * VS + gg * 16 + jt * 2) = make_uint2(hi, lo);
            }
        }
    };

    cp_k(0, 0);
    ldg_v(0);

    for (int T = 0; T < NTILES; T++) {
        const int buf = T & 1;
        cp_wait0();
        sts_v(buf);
        __syncthreads();
        if (T + 1 < NTILES) {
            cp_k(buf ^ 1, T + 1);
            ldg_v(T + 1);
        }

        const float*    kbuf = ks + buf * TROWS * KS;
        const uint32_t* vbuf = vs + buf * TROWS * VS;

#pragma unroll
        for (int nb = 0; nb < TROWS; nb += 8) {
            const int r0 = nb + tg;
            const int r1 = r0 + 4;
            uint32_t ah[4], al[4];
            tf32_split(kbuf[r0 * KS + kd0 + g],     ah[0], al[0]);
            tf32_split(kbuf[r0 * KS + kd0 + g + 8], ah[1], al[1]);
            tf32_split(kbuf[r1 * KS + kd0 + g],     ah[2], al[2]);
            tf32_split(kbuf[r1 * KS + kd0 + g + 8], ah[3], al[3]);
            const uint32_t* p0 = vbuf + r0 * VS + g * 16;
            const uint32_t* p1 = vbuf + r1 * VS + g * 16;
            uint4 b0[4], b1[4];
#pragma unroll
            for (int qv = 0; qv < 4; qv++) {
                b0[qv] = *(const uint4*)(p0 + qv * 4);
                b1[qv] = *(const uint4*)(p1 + qv * 4);
            }
            uint32_t BH0[8], BL0[8], BH1[8], BL1[8];
#pragma unroll
            for (int qv = 0; qv < 4; qv++) {
                BH0[2*qv] = b0[qv].x; BL0[2*qv] = b0[qv].y;
                BH0[2*qv+1] = b0[qv].z; BL0[2*qv+1] = b0[qv].w;
                BH1[2*qv] = b1[qv].x; BL1[2*qv] = b1[qv].y;
                BH1[2*qv+1] = b1[qv].z; BL1[2*qv+1] = b1[qv].w;
            }
#pragma unroll
            for (int jt = 0; jt < 8; jt++) {
                mma_tf32(acc[jt], ah[0], ah[1], ah[2], ah[3], BH0[jt], BH1[jt]);
                mma_tf32(acc[jt], ah[0], ah[1], ah[2], ah[3], BL0[jt], BL1[jt]);
                mma_tf32(acc[jt], al[0], al[1], al[2], al[3], BH0[jt], BH1[jt]);
            }
        }
    }

    float* p = g_part + ((long)(b * S1B + blk)) * (DKC * DVC);
#pragma unroll
    for (int jt = 0; jt < 8; jt++) {
        const int j = jt * 8 + 2 * tg;
        *(float2*)(p + (kd0 + g) * DVC + j)     = make_float2(acc[jt][0], acc[jt][1]);
        *(float2*)(p + (kd0 + g + 8) * DVC + j) = make_float2(acc[jt][2], acc[jt][3]);
    }
}

// ============================================================================
// Phase 1b: fold S1B partials -> g_ktv (16MB read, coalesced)
// ============================================================================
__global__ __launch_bounds__(256) void reduce_kernel()
{
    const int o = blockIdx.x * 256 + threadIdx.x;
    const int b = o >> 12;
    const int r = o & 4095;
    const float* p = g_part + (long)b * S1B * 4096 + r;
    float s = 0.f;
#pragma unroll 8
    for (int i = 0; i < S1B; i++) s += p[i * 4096];
    g_ktv[o] = s;
}

// ============================================================================
// Phase 2: out = q^T @ ktv  (R7's proven version: 52KB static smem,
// 4 blocks/SM; B splits in-loop). mma: m=n, k=dk, n'=j.
// ============================================================================
__global__ __launch_bounds__(128) void phase2_kernel(
    const float* __restrict__ q, float* __restrict__ out)
{
    __shared__ float qs[DKC * P2_QSTRIDE];   // 64 x 136 floats
    __shared__ float kt[DKC * P2_KSTRIDE];   // 64 x 72 floats

    const int b    = blockIdx.y;
    const int n0   = blockIdx.x * 128;
    const int t    = threadIdx.x;
    const int w    = t >> 5;
    const int lane = t & 31;
    const int g    = lane >> 2;
    const int tg   = lane & 3;

    {
        const float* src = g_ktv + b * (DKC * DVC);
#pragma unroll
        for (int i = 0; i < 32; i++) {
            int idx = t + i * 128;
            kt[(idx >> 6) * P2_KSTRIDE + (idx & 63)] = src[idx];
        }
    }
    {
        const float* qp = q + (long)b * DKC * NSEQ + n0 + t;
#pragma unroll 8
        for (int kd = 0; kd < DKC; kd++)
            qs[kd * P2_QSTRIDE + t] = qp[(long)kd * NSEQ];
    }
    __syncthreads();

    float acc[2][8][4];
#pragma unroll
    for (int mt = 0; mt < 2; mt++)
#pragma unroll
        for (int jt = 0; jt < 8; jt++)
#pragma unroll
            for (int p = 0; p < 4; p++) acc[mt][jt][p] = 0.f;

#pragma unroll
    for (int ksp = 0; ksp < 8; ksp++) {
        const int r0 = ksp * 8 + tg;
        const int r1 = r0 + 4;

        uint32_t bh[8][2], bl[8][2];
#pragma unroll
        for (int jt = 0; jt < 8; jt++) {
            tf32_split(kt[r0 * P2_KSTRIDE + jt * 8 + g], bh[jt][0], bl[jt][0]);
            tf32_split(kt[r1 * P2_KSTRIDE + jt * 8 + g], bh[jt][1], bl[jt][1]);
        }

#pragma unroll
        for (int mt = 0; mt < 2; mt++) {
            const int nb = 32 * w + 16 * mt;
            uint32_t ah[4], al[4];
            tf32_split(qs[r0 * P2_QSTRIDE + nb + g],     ah[0], al[0]);
            tf32_split(qs[r0 * P2_QSTRIDE + nb + g + 8], ah[1], al[1]);
            tf32_split(qs[r1 * P2_QSTRIDE + nb + g],     ah[2], al[2]);
            tf32_split(qs[r1 * P2_QSTRIDE + nb + g + 8], ah[3], al[3]);
#pragma unroll
            for (int jt = 0; jt < 8; jt++) {
                mma_tf32(acc[mt][jt], ah[0], ah[1], ah[2], ah[3], bh[jt][0], bh[jt][1]);
                mma_tf32(acc[mt][jt], ah[0], ah[1], ah[2], ah[3], bl[jt][0], bl[jt][1]);
                mma_tf32(acc[mt][jt], al[0], al[1], al[2], al[3], bh[jt][0], bh[jt][1]);
            }
        }
    }

#pragma unroll
    for (int mt = 0; mt < 2; mt++) {
        const int nrow = n0 + 32 * w + 16 * mt + g;
        float* o0 = out + ((long)b * NSEQ + nrow) * DVC;
        float* o1 = out + ((long)b * NSEQ + nrow + 8) * DVC;
#pragma unroll
        for (int jt = 0; jt < 8; jt++) {
            const int j = jt * 8 + 2 * tg;
            *(float2*)(o0 + j) = make_float2(acc[mt][jt][0], acc[mt][jt][1]);
            *(float2*)(o1 + j) = make_float2(acc[mt][jt][2], acc[mt][jt][3]);
        }
    }
}

extern "C" void kernel_launch(void* const* d_in, const int* in_sizes, int n_in,
                              void* d_out, int out_size)
{
    const float* q = (const float*)d_in[0];
    const float* k = (const float*)d_in[1];
    const float* v = (const float*)d_in[2];
    float* out = (float*)d_out;

    cudaFuncSetAttribute(phase1_kernel, cudaFuncAttributeMaxDynamicSharedMemorySize, P1_SMEM);

    phase1_kernel<<<dim3(S1B, BATCH), 128, P1_SMEM>>>(k, v);
    reduce_kernel<<<(BATCH * DKC * DVC) / 256, 256>>>();
    phase2_kernel<<<dim3(NSEQ / 128, BATCH), 128>>>(q, out);
}

// round 12
// speedup vs baseline: 1.2993x; 1.1517x over previous
#include <cuda_runtime.h>
#include <cstdint>

// LinearAttention: B=16, DK=64, N=8192, DV=64, fp32.
//   ktv[b,k,j] = sum_n k[b,n,k] * v[b,n,j]
//   out[b,n,j] = sum_k q[b,k,n] * ktv[b,k,j]
// Inputs: q [B,DK,N], k [B,N,DK], v [B,N,DV]. Output [B,N,DV] fp32.
//
// Tensor cores via mma.sync.m16n8k16.row.col.f32.bf16 (full-rate, K=16/instr),
// 3-term truncation split: x = hi(bf16, top 16 bits) + lo(bf16 of residual).
// Dropped term lo*lo ~2^-16 per product -> rel_err ~1e-5 << 1e-3.
// B operands pre-split+pre-paired in smem (packed [rowpair][g][jt][hi,lo]);
// A operands split in-loop (non-redundant per warp).

#define BATCH  16
#define DKC    64
#define NSEQ   8192
#define DVC    64
#define S1B    64                 // phase-1 blocks per batch
#define ROWS_PB (NSEQ / S1B)      // 128
#define TROWS  32
#define NTILES (ROWS_PB / TROWS)  // 4
#define KS     68                 // phase1 k fp32 smem stride (words)
#define VSP    136                // packed v words per n-rowpair
#define QS2    132                // phase2 q fp32 stride
#define KTP    136                // packed ktv words per dk-rowpair

#define P2_SMEM (DKC * QS2 * 4 + 32 * KTP * 4)   // 33792 + 17408 = 51200 B

__device__ float g_part[BATCH * S1B * DKC * DVC];  // 16 MB partial ktv
__device__ float g_ktv [BATCH * DKC * DVC];

// ---------------- helpers ----------------
__device__ __forceinline__ void cp16(uint32_t dst, const void* src) {
    asm volatile("cp.async.cg.shared.global [%0], [%1], 16;" :: "r"(dst), "l"(src));
}
__device__ __forceinline__ void cp_commit() { asm volatile("cp.async.commit_group;"); }
__device__ __forceinline__ void cp_wait0()  { asm volatile("cp.async.wait_group 0;"); }
__device__ __forceinline__ uint32_t smem_u32(const void* p) {
    uint32_t a;
    asm("{ .reg .u64 t; cvta.to.shared.u64 t, %1; cvt.u32.u64 %0, t; }" : "=r"(a) : "l"(p));
    return a;
}
// hi part of x as float: top 16 bits (exact bf16 by truncation)
__device__ __forceinline__ float trunc_hi(float x) {
    return __uint_as_float(__float_as_uint(x) & 0xFFFF0000u);
}
// pack {bf16_hi(x0) in low half, bf16_hi(x1) in high half} with one PRMT
__device__ __forceinline__ uint32_t prmt_hi(float x0, float x1) {
    uint32_t r;
    asm("prmt.b32 %0, %1, %2, 0x7632;" : "=r"(r)
        : "r"(__float_as_uint(x0)), "r"(__float_as_uint(x1)));
    return r;
}
// pack {bf16(l0) low, bf16(l1) high}
__device__ __forceinline__ uint32_t cvt_lo(float l0, float l1) {
    uint32_t r;
    asm("cvt.rn.bf16x2.f32 %0, %1, %2;" : "=r"(r) : "f"(l1), "f"(l0));
    return r;
}
// full split of a consecutive-k pair (x0 = even k -> low half)
__device__ __forceinline__ void split_pair(float x0, float x1,
                                           uint32_t& hi, uint32_t& lo) {
    hi = prmt_hi(x0, x1);
    lo = cvt_lo(x0 - trunc_hi(x0), x1 - trunc_hi(x1));
}
__device__ __forceinline__ void mma_bf16(float* d, const uint32_t* a,
                                         uint32_t b0, uint32_t b1) {
    asm volatile("mma.sync.aligned.m16n8k16.row.col.f32.bf16.bf16.f32 "
                 "{%0,%1,%2,%3}, {%4,%5,%6,%7}, {%8,%9}, {%0,%1,%2,%3};"
                 : "+f"(d[0]), "+f"(d[1]), "+f"(d[2]), "+f"(d[3])
                 : "r"(a[0]), "r"(a[1]), "r"(a[2]), "r"(a[3]), "r"(b0), "r"(b1));
}

// ============================================================================
// Phase 1: partial ktv = k_chunk^T @ v_chunk.
// Block 128 thr (4 warps). Warp w: dk rows [16w,16w+16) x all 64 j.
// mma m16n8k16: m=dk, k=n (16/instr), n'=j.
//   A = k_tile[n][dk] fp32 in smem, split+paired in-loop (PRMT/CVT).
//   B = v pre-split into packed [n-rowpair][g][jt][hi,lo] smem plane.
// k via cp.async double-buffer; v via LDG->split->STS double-buffer.
// ============================================================================
__global__ __launch_bounds__(128, 4) void phase1_kernel(
    const float* __restrict__ kmat, const float* __restrict__ vmat)
{
    __shared__ float    ks[2][TROWS * KS];     // 17408 B
    __shared__ uint32_t vs[2][16 * VSP];       // 17408 B

    const int b    = blockIdx.y;
    const int blk  = blockIdx.x;
    const int t    = threadIdx.x;
    const int w    = t >> 5;
    const int lane = t & 31;
    const int g    = lane >> 2;
    const int tg   = lane & 3;
    const int kd0  = 16 * w;

    float acc[8][4];
#pragma unroll
    for (int jt = 0; jt < 8; jt++)
#pragma unroll
        for (int p = 0; p < 4; p++) acc[jt][p] = 0.f;

    const long base = ((long)b * NSEQ + (long)blk * ROWS_PB) * 64;
    const float4* kg4 = (const float4*)(kmat + base);
    const float4* vg4 = (const float4*)(vmat + base);
    const uint32_t ks_addr = smem_u32(&ks[0][0]);

    auto cp_k = [&](int buf, int T) {
        const float4* kp = kg4 + T * 512;
        uint32_t kb = ks_addr + (uint32_t)buf * TROWS * KS * 4;
#pragma unroll
        for (int i = 0; i < 4; i++) {
            int idx = t + i * 128;
            int r = idx >> 4, c4 = idx & 15;
            cp16(kb + (uint32_t)(r * KS + c4 * 4) * 4, kp + idx);
        }
        cp_commit();
    };

    // v producer: 2 tasks/thread; task = (rp = n-rowpair 0..15, c4 = float4 col)
    float4 vA[2], vB[2];
    auto ldg_v = [&](int T) {
#pragma unroll
        for (int i = 0; i < 2; i++) {
            int task = t + i * 128;
            int rp = task >> 4, c4 = task & 15;
            vA[i] = vg4[T * 512 + (2 * rp) * 16 + c4];
            vB[i] = vg4[T * 512 + (2 * rp + 1) * 16 + c4];
        }
    };
    auto sts_v = [&](int buf) {
        uint32_t* vb = vs[buf];
#pragma unroll
        for (int i = 0; i < 2; i++) {
            int task = t + i * 128;
            int rp = task >> 4, c4 = task & 15;
            const float* f0 = (const float*)&vA[i];
            const float* f1 = (const float*)&vB[i];
#pragma unroll
            for (int e = 0; e < 4; e++) {
                int j = c4 * 4 + e;
                uint32_t hi, lo;
                split_pair(f0[e], f1[e], hi, lo);   // low half = even n row
                *(uint2*)(vb + rp * VSP + (j & 7) * 16 + (j >> 3) * 2) =
                    make_uint2(hi, lo);
            }
        }
    };

    cp_k(0, 0);
    ldg_v(0);

    for (int T = 0; T < NTILES; T++) {
        const int buf = T & 1;
        cp_wait0();
        sts_v(buf);
        __syncthreads();
        if (T + 1 < NTILES) {
            cp_k(buf ^ 1, T + 1);
            ldg_v(T + 1);
        }

        const float*    kb = ks[buf];
        const uint32_t* vb = vs[buf];

#pragma unroll
        for (int nc = 0; nc < 2; nc++) {          // two 16-row chunks
            const int n0 = nc * 16 + 2 * tg;      // even n of b0 pair
            const int n2 = n0 + 8;                // even n of b1 pair
            const int c0 = kd0 + g, c1 = c0 + 8;

            uint32_t ah[4], al[4];
            split_pair(kb[n0 * KS + c0], kb[(n0 + 1) * KS + c0], ah[0], al[0]);
            split_pair(kb[n0 * KS + c1], kb[(n0 + 1) * KS + c1], ah[1], al[1]);
            split_pair(kb[n2 * KS + c0], kb[(n2 + 1) * KS + c0], ah[2], al[2]);
            split_pair(kb[n2 * KS + c1], kb[(n2 + 1) * KS + c1], ah[3], al[3]);

            const uint32_t* p0 = vb + (nc * 8 + tg) * VSP + g * 16;
            const uint32_t* p1 = p0 + 4 * VSP;
#pragma unroll
            for (int qv = 0; qv < 4; qv++) {
                uint4 X0 = *(const uint4*)(p0 + qv * 4);
                uint4 X1 = *(const uint4*)(p1 + qv * 4);
                const int j0 = 2 * qv, j1 = j0 + 1;
                mma_bf16(acc[j0], ah, X0.x, X1.x);   // hi*hi
                mma_bf16(acc[j0], ah, X0.y, X1.y);   // hi*lo
                mma_bf16(acc[j0], al, X0.x, X1.x);   // lo*hi
                mma_bf16(acc[j1], ah, X0.z, X1.z);
                mma_bf16(acc[j1], ah, X0.w, X1.w);
                mma_bf16(acc[j1], al, X0.z, X1.z);
            }
        }
    }

    float* p = g_part + ((long)(b * S1B + blk)) * (DKC * DVC);
#pragma unroll
    for (int jt = 0; jt < 8; jt++) {
        const int j = jt * 8 + 2 * tg;
        *(float2*)(p + (kd0 + g) * DVC + j)     = make_float2(acc[jt][0], acc[jt][1]);
        *(float2*)(p + (kd0 + g + 8) * DVC + j) = make_float2(acc[jt][2], acc[jt][3]);
    }
}

// ============================================================================
// Phase 1b: fold S1B partials -> g_ktv (16MB read, coalesced)
// ============================================================================
__global__ __launch_bounds__(256) void reduce_kernel()
{
    const int o = blockIdx.x * 256 + threadIdx.x;
    const int b = o >> 12;
    const int r = o & 4095;
    const float* p = g_part + (long)b * S1B * 4096 + r;
    float s = 0.f;
#pragma unroll 8
    for (int i = 0; i < S1B; i++) s += p[i * 4096];
    g_ktv[o] = s;
}

// ============================================================================
// Phase 2: out = q^T @ ktv.
// Block 128 thr (4 warps), 128-row n-tile; warp w: n rows [32w,32w+32) (2 mt).
// mma m16n8k16: m=n, k=dk (16/instr), n'=j.
//   A = q_tile[dk][n] fp32 (split+paired along dk in-loop).
//   B = ktv pre-split packed [dk-rowpair][g][jt][hi,lo].
// 51.2 KB dynamic smem -> 4 blocks/SM.
// ============================================================================
__global__ __launch_bounds__(128) void phase2_kernel(
    const float* __restrict__ q, float* __restrict__ out)
{
    extern __shared__ uint32_t p2sm[];
    float*    qs = (float*)p2sm;          // [64][QS2]
    uint32_t* kp = p2sm + DKC * QS2;      // [32 rowpairs][KTP]

    const int b    = blockIdx.y;
    const int n0   = blockIdx.x * 128;
    const int t    = threadIdx.x;
    const int w    = t >> 5;
    const int lane = t & 31;
    const int g    = lane >> 2;
    const int tg   = lane & 3;

    // stage ktv: split + pair consecutive dk rows (4 tasks/thread)
    {
        const float4* src = (const float4*)(g_ktv + b * (DKC * DVC));
#pragma unroll
        for (int i = 0; i < 4; i++) {
            int task = t + i * 128;           // 0..511
            int rp = task >> 4, c4 = task & 15;
            float4 r0 = src[(2 * rp) * 16 + c4];
            float4 r1 = src[(2 * rp + 1) * 16 + c4];
            const float* f0 = (const float*)&r0;
            const float* f1 = (const float*)&r1;
#pragma unroll
            for (int e = 0; e < 4; e++) {
                int j = c4 * 4 + e;
                uint32_t hi, lo;
                split_pair(f0[e], f1[e], hi, lo);  // low half = even dk row
                *(uint2*)(kp + rp * KTP + (j & 7) * 16 + (j >> 3) * 2) =
                    make_uint2(hi, lo);
            }
        }
    }
    // stage q tile fp32 (coalesced along n)
    {
        const float* qp = q + (long)b * DKC * NSEQ + n0 + t;
#pragma unroll 8
        for (int kd = 0; kd < DKC; kd++)
            qs[kd * QS2 + t] = qp[(long)kd * NSEQ];
    }
    __syncthreads();

    float acc[2][8][4];
#pragma unroll
    for (int mt = 0; mt < 2; mt++)
#pragma unroll
        for (int jt = 0; jt < 8; jt++)
#pragma unroll
            for (int p = 0; p < 4; p++) acc[mt][jt][p] = 0.f;

#pragma unroll
    for (int c = 0; c < 4; c++) {                 // four 16-dk chunks
        const int d0 = 16 * c + 2 * tg;           // even dk of b0/a0 pair
        const int d2 = d0 + 8;                    // even dk of b1/a2 pair

        uint32_t ah[2][4], al[2][4];
#pragma unroll
        for (int mt = 0; mt < 2; mt++) {
            const int ncol = 32 * w + 16 * mt + g;
            split_pair(qs[d0 * QS2 + ncol],     qs[(d0 + 1) * QS2 + ncol],     ah[mt][0], al[mt][0]);
            split_pair(qs[d0 * QS2 + ncol + 8], qs[(d0 + 1) * QS2 + ncol + 8], ah[mt][1], al[mt][1]);
            split_pair(qs[d2 * QS2 + ncol],     qs[(d2 + 1) * QS2 + ncol],     ah[mt][2], al[mt][2]);
            split_pair(qs[d2 * QS2 + ncol + 8], qs[(d2 + 1) * QS2 + ncol + 8], ah[mt][3], al[mt][3]);
        }

        const uint32_t* p0 = kp + (8 * c + tg) * KTP + g * 16;
        const uint32_t* p1 = p0 + 4 * KTP;
#pragma unroll
        for (int qv = 0; qv < 4; qv++) {
            uint4 X0 = *(const uint4*)(p0 + qv * 4);
            uint4 X1 = *(const uint4*)(p1 + qv * 4);
            const int j0 = 2 * qv, j1 = j0 + 1;
#pragma unroll
            for (int mt = 0; mt < 2; mt++) {
                mma_bf16(acc[mt][j0], ah[mt], X0.x, X1.x);
                mma_bf16(acc[mt][j0], ah[mt], X0.y, X1.y);
                mma_bf16(acc[mt][j0], al[mt], X0.x, X1.x);
                mma_bf16(acc[mt][j1], ah[mt], X0.z, X1.z);
                mma_bf16(acc[mt][j1], ah[mt], X0.w, X1.w);
                mma_bf16(acc[mt][j1], al[mt], X0.z, X1.z);
            }
        }
    }

#pragma unroll
    for (int mt = 0; mt < 2; mt++) {
        const int nrow = n0 + 32 * w + 16 * mt + g;
        float* o0 = out + ((long)b * NSEQ + nrow) * DVC;
        float* o1 = out + ((long)b * NSEQ + nrow + 8) * DVC;
#pragma unroll
        for (int jt = 0; jt < 8; jt++) {
            const int j = jt * 8 + 2 * tg;
            *(float2*)(o0 + j) = make_float2(acc[mt][jt][0], acc[mt][jt][1]);
            *(float2*)(o1 + j) = make_float2(acc[mt][jt][2], acc[mt][jt][3]);
        }
    }
}

extern "C" void kernel_launch(void* const* d_in, const int* in_sizes, int n_in,
                              void* d_out, int out_size)
{
    const float* q = (const float*)d_in[0];
    const float* k = (const float*)d_in[1];
    const float* v = (const float*)d_in[2];
    float* out = (float*)d_out;

    cudaFuncSetAttribute(phase2_kernel, cudaFuncAttributeMaxDynamicSharedMemorySize, P2_SMEM);

    phase1_kernel<<<dim3(S1B, BATCH), 128>>>(k, v);
    reduce_kernel<<<(BATCH * DKC * DVC) / 256, 256>>>();
    phase2_kernel<<<dim3(NSEQ / 128, BATCH), 128, P2_SMEM>>>(q, out);
}